// round 6
// baseline (speedup 1.0000x reference)
#include <cuda_runtime.h>

#define Nn 128
#define Dd 512
#define NPAIR 8128            // C(128,2)
#define NTRI  341376          // C(128,3)
#define NROWS (Nn + NPAIR + NTRI)   // 349632
#define EPS   32.0f
#define SHARP 10.0f

__device__ float    g_d[Nn * Nn];     // pairwise distances (64 KB, L2-resident)
__device__ unsigned g_adj[Nn * 4];    // adjacency bitmask: bit j of g_adj[i*4+j/32]

// --- fused: distances + row norms + adjacency mask -------------------------
// block i; thread t: j = t>>2, slice s = t&3 (128 floats each).
__global__ void __launch_bounds__(512) k_dist(const float* __restrict__ W) {
    int i = blockIdx.x;
    int t = threadIdx.x;
    int j = t >> 2, s = t & 3;

    __shared__ float4 wi[Dd / 4];
    __shared__ float  sdot[Nn], ssq[Nn];
    __shared__ float  s_sqi;

    const float4* wg = reinterpret_cast<const float4*>(W + (size_t)i * Dd);
    if (t < Dd / 4) wi[t] = wg[t];
    __syncthreads();

    const float4* wj  = reinterpret_cast<const float4*>(W + (size_t)j * Dd) + s * 32;
    const float4* wis = wi + s * 32;
    float dot = 0.f, sq = 0.f;
#pragma unroll
    for (int k = 0; k < 32; k++) {
        float4 a = wis[k], b = wj[k];
        dot += a.x * b.x; dot += a.y * b.y; dot += a.z * b.z; dot += a.w * b.w;
        sq  += b.x * b.x; sq  += b.y * b.y; sq  += b.z * b.z; sq  += b.w * b.w;
    }
    // reduce across the 4 slices (lanes 4j..4j+3 of the same warp)
    dot += __shfl_xor_sync(0xffffffffu, dot, 1);
    dot += __shfl_xor_sync(0xffffffffu, dot, 2);
    sq  += __shfl_xor_sync(0xffffffffu, sq, 1);
    sq  += __shfl_xor_sync(0xffffffffu, sq, 2);
    if (s == 0) { sdot[j] = dot; ssq[j] = sq; }
    __syncthreads();

    if (t < Nn) {
        if (t == i) s_sqi = sdot[t];    // dot(i,i) == ||W_i||^2
    }
    __syncthreads();

    if (t < Nn) {
        float d2 = s_sqi + ssq[t] - 2.f * sdot[t];
        float d  = sqrtf(fmaxf(d2, 0.f));
        g_d[i * Nn + t] = d;
        unsigned bits = __ballot_sync(0xffffffffu, d <= EPS);
        if ((t & 31) == 0) g_adj[i * 4 + (t >> 5)] = bits;
    }
}

// --- combinatorics helpers --------------------------------------------------
__device__ __forceinline__ int C3f(int x) { return x * (x - 1) * (x - 2) / 6; }
__device__ __forceinline__ int off3(int i) { return C3f(Nn) - C3f(Nn - i); }
__device__ __forceinline__ int pairoff(int i) { return i * (2 * Nn - 1 - i) / 2; }
__device__ __forceinline__ bool adj(int a, int b) {
    return (g_adj[a * 4 + (b >> 5)] >> (b & 31)) & 1u;
}

__device__ __forceinline__ void setcol(float4& v, int col, int c0, float val) {
    if (col == c0)          v.x = val;
    else if (col == c0 + 1) v.y = val;
    else if (col == c0 + 2) v.z = val;
    else if (col == c0 + 3) v.w = val;
}

// --- output fill: one thread per float4; warp == one output row -------------
__global__ void __launch_bounds__(256) k_fill(float4* __restrict__ out) {
    int idx = blockIdx.x * 256 + threadIdx.x;   // < NROWS * 32
    int r  = idx >> 5;          // output row (uniform per warp)
    int c0 = (idx & 31) << 2;   // first column of this float4
    float4 v = make_float4(0.f, 0.f, 0.f, 0.f);

    if (r < Nn) {
        setcol(v, r, c0, 1.0f);
    } else if (r < Nn + NPAIR) {
        int p = r - Nn;
        // unrank p -> (i, j)
        int i = (int)((255.0f - sqrtf(65025.0f - 8.0f * (float)p)) * 0.5f);
        while (pairoff(i + 1) <= p) i++;
        while (pairoff(i) > p) i--;
        int j = i + 1 + (p - pairoff(i));
        float d = g_d[i * Nn + j];                 // warp-broadcast, L2 hit
        float val = 1.f / (1.f + expf(-SHARP * (EPS - d)));
        setcol(v, i, c0, val);
        setcol(v, j, c0, val);
    } else {
        int t = r - Nn - NPAIR;
        // unrank t -> (i, j, k)
        int rem = C3f(Nn) - t;                     // = C3(Nn - i) lower bound
        int i = Nn - (int)cbrtf(6.0f * (float)rem) - 2;
        if (i < 0) i = 0;
        while (i < Nn - 3 && off3(i + 1) <= t) i++;
        while (i > 0 && off3(i) > t) i--;
        int tp = t - off3(i);
        int M  = Nn - 1 - i;                       // items after i
        float tm = (float)(2 * M - 1);
        int jp = (int)((tm - sqrtf(tm * tm - 8.0f * (float)tp)) * 0.5f);
        if (jp < 0) jp = 0;
        while (jp * (2 * M - 1 - jp) / 2 > tp) jp--;
        while ((jp + 1) * (2 * M - 2 - jp) / 2 <= tp) jp++;
        int kp = jp + 1 + (tp - jp * (2 * M - 1 - jp) / 2);
        int j = i + 1 + jp;
        int k = i + 1 + kp;
        float val = (adj(i, j) && adj(j, k) && adj(i, k)) ? 1.0f : 0.0f;
        setcol(v, i, c0, val);
        setcol(v, j, c0, val);
        setcol(v, k, c0, val);
    }
    __stcs(&out[idx], v);            // streaming store, evict-first
}

extern "C" void kernel_launch(void* const* d_in, const int* in_sizes, int n_in,
                              void* d_out, int out_size) {
    const float* W = (const float*)d_in[0];
    float4* out = (float4*)d_out;

    k_dist<<<Nn, 512>>>(W);          // distances + adjacency mask (fused)

    int total4 = NROWS * 32;         // 11,188,224 float4 stores
    k_fill<<<total4 / 256, 256>>>(out);
}

// round 7
// speedup vs baseline: 1.0053x; 1.0053x over previous
#include <cuda_runtime.h>

#define Nn 128
#define Dd 512
#define NPAIR 8128            // C(128,2)
#define NTRI  341376          // C(128,3)
#define NROWS (Nn + NPAIR + NTRI)   // 349632
#define EPS   32.0f
#define SHARP 10.0f

__device__ float    g_d[Nn * Nn];     // pairwise distances (64 KB, L2-resident)
__device__ unsigned g_adj[Nn * 4];    // adjacency bitmask: bit j of g_adj[i*4+j/32]

// --- fused: distances + row norms + adjacency mask -------------------------
// block i; thread t: j = t>>2, slice s = t&3 (128 floats each).
__global__ void __launch_bounds__(512) k_dist(const float* __restrict__ W) {
    int i = blockIdx.x;
    int t = threadIdx.x;
    int j = t >> 2, s = t & 3;

    __shared__ float4 wi[Dd / 4];
    __shared__ float  sdot[Nn], ssq[Nn];
    __shared__ float  s_sqi;

    const float4* wg = reinterpret_cast<const float4*>(W + (size_t)i * Dd);
    if (t < Dd / 4) wi[t] = wg[t];
    __syncthreads();

    const float4* wj  = reinterpret_cast<const float4*>(W + (size_t)j * Dd) + s * 32;
    const float4* wis = wi + s * 32;
    float dot = 0.f, sq = 0.f;
#pragma unroll
    for (int k = 0; k < 32; k++) {
        float4 a = wis[k], b = wj[k];
        dot += a.x * b.x; dot += a.y * b.y; dot += a.z * b.z; dot += a.w * b.w;
        sq  += b.x * b.x; sq  += b.y * b.y; sq  += b.z * b.z; sq  += b.w * b.w;
    }
    // reduce across the 4 slices (lanes 4j..4j+3 of the same warp)
    dot += __shfl_xor_sync(0xffffffffu, dot, 1);
    dot += __shfl_xor_sync(0xffffffffu, dot, 2);
    sq  += __shfl_xor_sync(0xffffffffu, sq, 1);
    sq  += __shfl_xor_sync(0xffffffffu, sq, 2);
    if (s == 0) { sdot[j] = dot; ssq[j] = sq; }
    __syncthreads();

    if (t < Nn) {
        if (t == i) s_sqi = sdot[t];    // dot(i,i) == ||W_i||^2
    }
    __syncthreads();

    if (t < Nn) {
        float d2 = s_sqi + ssq[t] - 2.f * sdot[t];
        float d  = sqrtf(fmaxf(d2, 0.f));
        g_d[i * Nn + t] = d;
        unsigned bits = __ballot_sync(0xffffffffu, d <= EPS);
        if ((t & 31) == 0) g_adj[i * 4 + (t >> 5)] = bits;
    }
}

// --- combinatorics helpers --------------------------------------------------
__device__ __forceinline__ int C3f(int x) { return x * (x - 1) * (x - 2) / 6; }
__device__ __forceinline__ int off3(int i) { return C3f(Nn) - C3f(Nn - i); }
__device__ __forceinline__ int pairoff(int i) { return i * (2 * Nn - 1 - i) / 2; }
__device__ __forceinline__ bool adj(int a, int b) {
    return (g_adj[a * 4 + (b >> 5)] >> (b & 31)) & 1u;
}

__device__ __forceinline__ void setcol(float4& v, int col, int c0, float val) {
    if (col == c0)          v.x = val;
    else if (col == c0 + 1) v.y = val;
    else if (col == c0 + 2) v.z = val;
    else if (col == c0 + 3) v.w = val;
}

// --- output fill: one thread per float4; warp == one output row -------------
__global__ void __launch_bounds__(256) k_fill(float4* __restrict__ out) {
    int idx = blockIdx.x * 256 + threadIdx.x;   // < NROWS * 32
    int r  = idx >> 5;          // output row (uniform per warp)
    int c0 = (idx & 31) << 2;   // first column of this float4
    float4 v = make_float4(0.f, 0.f, 0.f, 0.f);

    if (r < Nn) {
        setcol(v, r, c0, 1.0f);
    } else if (r < Nn + NPAIR) {
        int p = r - Nn;
        // unrank p -> (i, j)
        int i = (int)((255.0f - sqrtf(65025.0f - 8.0f * (float)p)) * 0.5f);
        while (pairoff(i + 1) <= p) i++;
        while (pairoff(i) > p) i--;
        int j = i + 1 + (p - pairoff(i));
        float d = g_d[i * Nn + j];                 // warp-broadcast, L2 hit
        float val = 1.f / (1.f + expf(-SHARP * (EPS - d)));
        setcol(v, i, c0, val);
        setcol(v, j, c0, val);
    } else {
        int t = r - Nn - NPAIR;
        // unrank t -> (i, j, k)
        int rem = C3f(Nn) - t;                     // = C3(Nn - i) lower bound
        int i = Nn - (int)cbrtf(6.0f * (float)rem) - 2;
        if (i < 0) i = 0;
        while (i < Nn - 3 && off3(i + 1) <= t) i++;
        while (i > 0 && off3(i) > t) i--;
        int tp = t - off3(i);
        int M  = Nn - 1 - i;                       // items after i
        float tm = (float)(2 * M - 1);
        int jp = (int)((tm - sqrtf(tm * tm - 8.0f * (float)tp)) * 0.5f);
        if (jp < 0) jp = 0;
        while (jp * (2 * M - 1 - jp) / 2 > tp) jp--;
        while ((jp + 1) * (2 * M - 2 - jp) / 2 <= tp) jp++;
        int kp = jp + 1 + (tp - jp * (2 * M - 1 - jp) / 2);
        int j = i + 1 + jp;
        int k = i + 1 + kp;
        float val = (adj(i, j) && adj(j, k) && adj(i, k)) ? 1.0f : 0.0f;
        setcol(v, i, c0, val);
        setcol(v, j, c0, val);
        setcol(v, k, c0, val);
    }
    __stcs(&out[idx], v);            // streaming store, evict-first
}

extern "C" void kernel_launch(void* const* d_in, const int* in_sizes, int n_in,
                              void* d_out, int out_size) {
    const float* W = (const float*)d_in[0];
    float4* out = (float4*)d_out;

    k_dist<<<Nn, 512>>>(W);          // distances + adjacency mask (fused)

    int total4 = NROWS * 32;         // 11,188,224 float4 stores
    k_fill<<<total4 / 256, 256>>>(out);
}

// round 8
// speedup vs baseline: 1.0080x; 1.0027x over previous
#include <cuda_runtime.h>

#define Nn 128
#define Dd 512
#define NPAIR 8128            // C(128,2)
#define NTRI  341376          // C(128,3)
#define NROWS (Nn + NPAIR + NTRI)   // 349632
#define EPS   32.0f
#define SHARP 10.0f

__device__ float    g_d[Nn * Nn];     // pairwise distances (64 KB, L2-resident)
__device__ unsigned g_adj[Nn * 4];    // adjacency bitmask: bit j of g_adj[i*4+j/32]

// --- fused: distances + row norms + adjacency mask -------------------------
// block i; thread t: j = t>>2, slice s = t&3 (128 floats each).
__global__ void __launch_bounds__(512) k_dist(const float* __restrict__ W) {
    int i = blockIdx.x;
    int t = threadIdx.x;
    int j = t >> 2, s = t & 3;

    __shared__ float4 wi[Dd / 4];
    __shared__ float  sdot[Nn], ssq[Nn];
    __shared__ float  s_sqi;

    const float4* wg = reinterpret_cast<const float4*>(W + (size_t)i * Dd);
    if (t < Dd / 4) wi[t] = wg[t];
    __syncthreads();

    const float4* wj  = reinterpret_cast<const float4*>(W + (size_t)j * Dd) + s * 32;
    const float4* wis = wi + s * 32;
    float dot = 0.f, sq = 0.f;
#pragma unroll
    for (int k = 0; k < 32; k++) {
        float4 a = wis[k], b = wj[k];
        dot += a.x * b.x; dot += a.y * b.y; dot += a.z * b.z; dot += a.w * b.w;
        sq  += b.x * b.x; sq  += b.y * b.y; sq  += b.z * b.z; sq  += b.w * b.w;
    }
    // reduce across the 4 slices (lanes 4j..4j+3 of the same warp)
    dot += __shfl_xor_sync(0xffffffffu, dot, 1);
    dot += __shfl_xor_sync(0xffffffffu, dot, 2);
    sq  += __shfl_xor_sync(0xffffffffu, sq, 1);
    sq  += __shfl_xor_sync(0xffffffffu, sq, 2);
    if (s == 0) { sdot[j] = dot; ssq[j] = sq; }
    __syncthreads();

    if (t < Nn) {
        if (t == i) s_sqi = sdot[t];    // dot(i,i) == ||W_i||^2
    }
    __syncthreads();

    if (t < Nn) {
        float d2 = s_sqi + ssq[t] - 2.f * sdot[t];
        float d  = sqrtf(fmaxf(d2, 0.f));
        g_d[i * Nn + t] = d;
        unsigned bits = __ballot_sync(0xffffffffu, d <= EPS);
        if ((t & 31) == 0) g_adj[i * 4 + (t >> 5)] = bits;
    }
}

// --- combinatorics helpers --------------------------------------------------
__device__ __forceinline__ int C3f(int x) { return x * (x - 1) * (x - 2) / 6; }
__device__ __forceinline__ int off3(int i) { return C3f(Nn) - C3f(Nn - i); }
__device__ __forceinline__ int pairoff(int i) { return i * (2 * Nn - 1 - i) / 2; }
__device__ __forceinline__ bool adj(int a, int b) {
    return (g_adj[a * 4 + (b >> 5)] >> (b & 31)) & 1u;
}

__device__ __forceinline__ void setcol(float4& v, int col, int c0, float val) {
    if (col == c0)          v.x = val;
    else if (col == c0 + 1) v.y = val;
    else if (col == c0 + 2) v.z = val;
    else if (col == c0 + 3) v.w = val;
}

// --- output fill: one thread per float4; warp == one output row -------------
__global__ void __launch_bounds__(256) k_fill(float4* __restrict__ out) {
    int idx = blockIdx.x * 256 + threadIdx.x;   // < NROWS * 32
    int r  = idx >> 5;          // output row (uniform per warp)
    int c0 = (idx & 31) << 2;   // first column of this float4
    float4 v = make_float4(0.f, 0.f, 0.f, 0.f);

    if (r < Nn) {
        setcol(v, r, c0, 1.0f);
    } else if (r < Nn + NPAIR) {
        int p = r - Nn;
        // unrank p -> (i, j)
        int i = (int)((255.0f - sqrtf(65025.0f - 8.0f * (float)p)) * 0.5f);
        while (pairoff(i + 1) <= p) i++;
        while (pairoff(i) > p) i--;
        int j = i + 1 + (p - pairoff(i));
        float d = g_d[i * Nn + j];                 // warp-broadcast, L2 hit
        float val = 1.f / (1.f + expf(-SHARP * (EPS - d)));
        setcol(v, i, c0, val);
        setcol(v, j, c0, val);
    } else {
        int t = r - Nn - NPAIR;
        // unrank t -> (i, j, k)
        int rem = C3f(Nn) - t;                     // = C3(Nn - i) lower bound
        int i = Nn - (int)cbrtf(6.0f * (float)rem) - 2;
        if (i < 0) i = 0;
        while (i < Nn - 3 && off3(i + 1) <= t) i++;
        while (i > 0 && off3(i) > t) i--;
        int tp = t - off3(i);
        int M  = Nn - 1 - i;                       // items after i
        float tm = (float)(2 * M - 1);
        int jp = (int)((tm - sqrtf(tm * tm - 8.0f * (float)tp)) * 0.5f);
        if (jp < 0) jp = 0;
        while (jp * (2 * M - 1 - jp) / 2 > tp) jp--;
        while ((jp + 1) * (2 * M - 2 - jp) / 2 <= tp) jp++;
        int kp = jp + 1 + (tp - jp * (2 * M - 1 - jp) / 2);
        int j = i + 1 + jp;
        int k = i + 1 + kp;
        float val = (adj(i, j) && adj(j, k) && adj(i, k)) ? 1.0f : 0.0f;
        setcol(v, i, c0, val);
        setcol(v, j, c0, val);
        setcol(v, k, c0, val);
    }
    __stcs(&out[idx], v);            // streaming store, evict-first
}

extern "C" void kernel_launch(void* const* d_in, const int* in_sizes, int n_in,
                              void* d_out, int out_size) {
    const float* W = (const float*)d_in[0];
    float4* out = (float4*)d_out;

    k_dist<<<Nn, 512>>>(W);          // distances + adjacency mask (fused)

    int total4 = NROWS * 32;         // 11,188,224 float4 stores
    k_fill<<<total4 / 256, 256>>>(out);
}